// round 14
// baseline (speedup 1.0000x reference)
#include <cuda_runtime.h>
#include <cuda_fp16.h>

#define NB 16384
#define NSTEPS 100
#define DTC 0.01f
#define SQDT 0.1f
#define SIG0 0.5f

typedef unsigned int u32;
typedef unsigned long long u64;

__device__ __forceinline__ u32 h2u(__half2 h) {
    u32 r; *(__half2*)&r = h; return r;
}
__device__ __forceinline__ __half2 u2h(u32 u) {
    __half2 h; *(u32*)&h = u; return h;
}

__device__ __forceinline__ void mma16816(float* d, const u32 a0, const u32 a1,
                                         const u32 a2, const u32 a3,
                                         const u32 b0, const u32 b1) {
    asm volatile(
        "mma.sync.aligned.m16n8k16.row.col.f32.f16.f16.f32 "
        "{%0,%1,%2,%3}, {%4,%5,%6,%7}, {%8,%9}, {%0,%1,%2,%3};"
        : "+f"(d[0]), "+f"(d[1]), "+f"(d[2]), "+f"(d[3])
        : "r"(a0), "r"(a1), "r"(a2), "r"(a3), "r"(b0), "r"(b1));
}
// fp16-accumulator layer-1 MMA: D (2x half2) = A(16x8) * B(8x8) + D
__device__ __forceinline__ void mma16808h(u32* d, const u32 a0, const u32 a1,
                                          const u32 b0) {
    asm volatile(
        "mma.sync.aligned.m16n8k8.row.col.f16.f16.f16.f16 "
        "{%0,%1}, {%2,%3}, {%4}, {%0,%1};"
        : "+r"(d[0]), "+r"(d[1])
        : "r"(a0), "r"(a1), "r"(b0));
}

__device__ float g_partials[128];
__device__ unsigned int g_count = 0;

__global__ __launch_bounds__(256) void bsde_mma(
    const float* __restrict__ y0, const float* __restrict__ Y0,
    const float* __restrict__ zW1, const float* __restrict__ zb1,
    const float* __restrict__ zW2, const float* __restrict__ zb2,
    const float* __restrict__ zW3, const float* __restrict__ zb3,
    const float* __restrict__ qW1, const float* __restrict__ qb1,
    const float* __restrict__ qW2, const float* __restrict__ qb2,
    const float* __restrict__ qW3, const float* __restrict__ qb3,
    const float* __restrict__ dW, const float* __restrict__ dZ,
    float* __restrict__ out)
{
    // W2 staging: pos = n*16 + kt*4 + tq.  [0]=z (hoisted to regs), [1]=q (read in-loop)
    __shared__ u64 W2S[2][1024];
    // layer-3 B-fragments: [m][kt3][tq][g], u64 = (b0, b1)
    __shared__ u64 W3BS[2][4][4][8];
    // b2 as half2: [m][nt][tq] = (b2[8nt+2tq], b2[8nt+2tq+1])
    __shared__ u32 B2H[2][8][4];
    __shared__ float B3S[2][4];
    __shared__ float red[256];
    __shared__ int   is_last;

    const int tx = threadIdx.x;
    const int l  = tx & 31;
    const int w  = tx >> 5;          // 8 warps, each owns 16 paths
    const int g  = l >> 2;
    const int tq = l & 3;

    // ---------------- stage W2 ----------------
    for (int idx = tx; idx < 4096; idx += 256) {
        int k = idx >> 6, n = idx & 63;
        int kt = k >> 4, r = k & 15;
        int tt, slot;
        if (r < 8) { tt = r >> 1; slot = r & 1; }
        else       { tt = (r - 8) >> 1; slot = 2 + (r & 1); }
        int pos = n * 16 + kt * 4 + tt;
        ((__half*)&W2S[0][pos])[slot] = __float2half_rn(zW2[idx]);
        ((__half*)&W2S[1][pos])[slot] = __float2half_rn(qW2[idx]);
    }
    // ---------------- stage W3 B-fragments (zero-padded to 8 cols) ----------------
    if (tx < 256) {
        int idx = tx;
        int g5 = idx & 7, tq5 = (idx >> 3) & 3, kt5 = (idx >> 5) & 3, m5 = idx >> 7;
        int k0 = 16 * kt5 + 2 * tq5;
        float w00, w01, w10, w11;
        if (m5 == 0) {
            w00 = (g5 < 3) ? zW3[k0 * 3 + g5] : 0.f;
            w01 = (g5 < 3) ? zW3[(k0 + 1) * 3 + g5] : 0.f;
            w10 = (g5 < 3) ? zW3[(k0 + 8) * 3 + g5] : 0.f;
            w11 = (g5 < 3) ? zW3[(k0 + 9) * 3 + g5] : 0.f;
        } else {
            w00 = (g5 == 0) ? qW3[k0] : 0.f;
            w01 = (g5 == 0) ? qW3[k0 + 1] : 0.f;
            w10 = (g5 == 0) ? qW3[k0 + 8] : 0.f;
            w11 = (g5 == 0) ? qW3[k0 + 9] : 0.f;
        }
        u64 v = (u64)h2u(__floats2half2_rn(w00, w01))
              | ((u64)h2u(__floats2half2_rn(w10, w11)) << 32);
        W3BS[m5][kt5][tq5][g5] = v;
    }
    if (tx < 64) {
        int idx = tx;
        int tq6 = idx & 3, nt6 = (idx >> 2) & 7, m6 = idx >> 5;
        const float* b2 = m6 ? qb2 : zb2;
        int n = 8 * nt6 + 2 * tq6;
        B2H[m6][nt6][tq6] = h2u(__floats2half2_rn(b2[n], b2[n + 1]));
    }
    if (tx < 4) {
        B3S[0][tx] = (tx < 3) ? zb3[tx] : 0.f;
        B3S[1][tx] = (tx == 0) ? qb3[0] : 0.f;
    }
    __syncthreads();

    // ---------------- hoist z-MLP layer-2 B fragments to regs ----------------
    u32 Bzl[4][8], Bzh[4][8];
    #pragma unroll
    for (int kt = 0; kt < 4; ++kt)
        #pragma unroll
        for (int nt = 0; nt < 8; ++nt) {
            u64 b = W2S[0][(8 * nt + g) * 16 + kt * 4 + tq];
            Bzl[kt][nt] = (u32)b;
            Bzh[kt][nt] = (u32)(b >> 32);
        }
    // q-MLP B base (u64 index); per-access offset = 128*nt + 4*kt (immediates)
    const u64* Wq = &W2S[1][g * 16 + tq];

    // ---------------- layer-1 B fragments (K=8: rows t,y,1,0..) ----------------
    u32 W1Bf[2][8];
    #pragma unroll
    for (int m = 0; m < 2; ++m) {
        const float* W1 = m ? qW1 : zW1;
        const float* b1 = m ? qb1 : zb1;
        #pragma unroll
        for (int nt1 = 0; nt1 < 8; ++nt1) {
            int n = 8 * nt1 + g;
            u32 v = 0;
            if (tq == 0)      v = h2u(__floats2half2_rn(W1[n], W1[64 + n]));
            else if (tq == 1) v = h2u(__floats2half2_rn(b1[n], 0.f));
            W1Bf[m][nt1] = v;
        }
    }

    // ---------------- per-path state: lane l < 16 owns path base + l ----------------
    const int path = blockIdx.x * 128 + w * 16 + (l & 15);
    const bool owner = (l < 16);
    float y = y0[0], Yv = Y0[0], t = 0.f, loss = 0.f;
    const float* dWp = dW + path * 3;
    const float* dZp = dZ + path * 3;

    #pragma unroll 1
    for (int i = 0; i < NSTEPS; ++i) {
        float dw0 = 0.f, dw1 = 0.f, dw2 = 0.f, dz0 = 0.f, dz1 = 0.f, dz2 = 0.f;
        if (owner) {
            dw0 = dWp[0] * SQDT; dw1 = dWp[1] * SQDT; dw2 = dWp[2] * SQDT;
            dz0 = dZp[0] * SQDT; dz1 = dZp[1] * SQDT; dz2 = dZp[2] * SQDT;
        }
        dWp += NB * 3; dZp += NB * 3;

        // y for rows g, g+8 of this warp's 16-path tile
        float yg  = __shfl_sync(0xffffffffu, y, g, 32);
        float yg8 = __shfl_sync(0xffffffffu, y, g + 8, 32);

        // layer-1 A fragment: A[p][k] = (t, y_p, 1, 0...) -- shared by z and q
        u32 a1_0, a1_1;
        if (tq == 0) {
            a1_0 = h2u(__floats2half2_rn(t, yg));
            a1_1 = h2u(__floats2half2_rn(t, yg8));
        } else if (tq == 1) {
            a1_0 = 0x00003C00u;   // half2(1.0, 0.0)
            a1_1 = 0x00003C00u;
        } else {
            a1_0 = 0u;
            a1_1 = 0u;
        }

        // ---- layer 1: fp16-accum MMAs for BOTH MLPs (16 independent) ----
        u32 D1h[2][8][2];
        #pragma unroll
        for (int m = 0; m < 2; ++m)
            #pragma unroll
            for (int nt1 = 0; nt1 < 8; ++nt1) {
                D1h[m][nt1][0] = 0u; D1h[m][nt1][1] = 0u;
                mma16808h(D1h[m][nt1], a1_0, a1_1, W1Bf[m][nt1]);
            }

        // ---- relu (hmax2) -> layer-2 A fragments, both MLPs ----
        u32 A2[2][4][4];
        const __half2 z2 = __floats2half2_rn(0.f, 0.f);
        #pragma unroll
        for (int m = 0; m < 2; ++m)
            #pragma unroll
            for (int kt = 0; kt < 4; ++kt) {
                A2[m][kt][0] = h2u(__hmax2(u2h(D1h[m][2 * kt][0]), z2));
                A2[m][kt][1] = h2u(__hmax2(u2h(D1h[m][2 * kt][1]), z2));
                A2[m][kt][2] = h2u(__hmax2(u2h(D1h[m][2 * kt + 1][0]), z2));
                A2[m][kt][3] = h2u(__hmax2(u2h(D1h[m][2 * kt + 1][1]), z2));
            }

        // ---- layer 2: z/q interleaved (z B from regs, q B from smem) ----
        float daccz[8][4], daccq[8][4];
        #pragma unroll
        for (int nt = 0; nt < 8; ++nt)
            #pragma unroll
            for (int j = 0; j < 4; ++j) { daccz[nt][j] = 0.f; daccq[nt][j] = 0.f; }

        #pragma unroll
        for (int kt = 0; kt < 4; ++kt) {
            #pragma unroll
            for (int nt = 0; nt < 8; ++nt) {
                mma16816(daccz[nt],
                         A2[0][kt][0], A2[0][kt][1], A2[0][kt][2], A2[0][kt][3],
                         Bzl[kt][nt], Bzh[kt][nt]);
                u64 bq = Wq[128 * nt + 4 * kt];
                mma16816(daccq[nt],
                         A2[1][kt][0], A2[1][kt][1], A2[1][kt][2], A2[1][kt][3],
                         (u32)bq, (u32)(bq >> 32));
            }
        }

        // ---- +b2, relu, pack -> layer-3 A fragments, both MLPs ----
        u32 A3[2][4][4];
        #pragma unroll
        for (int m = 0; m < 2; ++m) {
            const float(*da)[4] = m ? daccq : daccz;
            #pragma unroll
            for (int kt3 = 0; kt3 < 4; ++kt3) {
                __half2 b2a = u2h(B2H[m][2 * kt3][tq]);
                __half2 b2b = u2h(B2H[m][2 * kt3 + 1][tq]);
                __half2 v;
                v = __hadd2(__floats2half2_rn(da[2 * kt3][0], da[2 * kt3][1]), b2a);
                A3[m][kt3][0] = h2u(__hmax2(v, z2));
                v = __hadd2(__floats2half2_rn(da[2 * kt3][2], da[2 * kt3][3]), b2a);
                A3[m][kt3][1] = h2u(__hmax2(v, z2));
                v = __hadd2(__floats2half2_rn(da[2 * kt3 + 1][0], da[2 * kt3 + 1][1]), b2b);
                A3[m][kt3][2] = h2u(__hmax2(v, z2));
                v = __hadd2(__floats2half2_rn(da[2 * kt3 + 1][2], da[2 * kt3 + 1][3]), b2b);
                A3[m][kt3][3] = h2u(__hmax2(v, z2));
            }
        }

        // ---- layer 3: 4 short chains (z/q x kt-halves), interleaved ----
        float D3za[4] = {0.f, 0.f, 0.f, 0.f}, D3zb[4] = {0.f, 0.f, 0.f, 0.f};
        float D3qa[4] = {0.f, 0.f, 0.f, 0.f}, D3qb[4] = {0.f, 0.f, 0.f, 0.f};
        #pragma unroll
        for (int h = 0; h < 2; ++h) {   // h=0: kt3 {0,2}; h=1: kt3 {1,3}
            u64 w3;
            w3 = W3BS[0][h][tq][g];
            mma16816(D3za, A3[0][h][0], A3[0][h][1], A3[0][h][2], A3[0][h][3],
                     (u32)w3, (u32)(w3 >> 32));
            w3 = W3BS[1][h][tq][g];
            mma16816(D3qa, A3[1][h][0], A3[1][h][1], A3[1][h][2], A3[1][h][3],
                     (u32)w3, (u32)(w3 >> 32));
            w3 = W3BS[0][2 + h][tq][g];
            mma16816(D3zb, A3[0][2 + h][0], A3[0][2 + h][1], A3[0][2 + h][2], A3[0][2 + h][3],
                     (u32)w3, (u32)(w3 >> 32));
            w3 = W3BS[1][2 + h][tq][g];
            mma16816(D3qb, A3[1][2 + h][0], A3[1][2 + h][1], A3[1][2 + h][2], A3[1][2 + h][3],
                     (u32)w3, (u32)(w3 >> 32));
        }
        float zd0 = D3za[0] + D3zb[0];
        float zd1 = D3za[1] + D3zb[1];
        float zd2 = D3za[2] + D3zb[2];
        float zd3 = D3za[3] + D3zb[3];
        float qd0 = D3qa[0] + D3qb[0];
        float qd2 = D3qa[2] + D3qb[2];

        // ---- redistribute: path p reads D3[p][col] ----
        // D3 frag: d0=(g,2tq) d1=(g,2tq+1) d2=(g+8,2tq) d3=(g+8,2tq+1)
        const int srcA = 4 * (l & 7);
        const bool hi8 = (l & 8) != 0;
        float va, vb;
        va = __shfl_sync(0xffffffffu, zd0, srcA, 32);
        vb = __shfl_sync(0xffffffffu, zd2, srcA, 32);
        float zo0 = (hi8 ? vb : va) + B3S[0][0];
        va = __shfl_sync(0xffffffffu, zd1, srcA, 32);
        vb = __shfl_sync(0xffffffffu, zd3, srcA, 32);
        float zo1 = (hi8 ? vb : va) + B3S[0][1];
        va = __shfl_sync(0xffffffffu, zd0, srcA + 1, 32);
        vb = __shfl_sync(0xffffffffu, zd2, srcA + 1, 32);
        float zo2 = (hi8 ? vb : va) + B3S[0][2];
        va = __shfl_sync(0xffffffffu, qd0, srcA, 32);
        vb = __shfl_sync(0xffffffffu, qd2, srcA, 32);
        float qvv = (hi8 ? vb : va) + B3S[1][0];

        // ---- SDE / BSDE update (residual = z.dw - z.dz; Y cancels) ----
        if (owner) {
            float zdw = zo0 * dw0 + zo1 * dw1 + zo2 * dw2;
            float zdz = zo0 * dz0 + zo1 * dz1 + zo2 * dz2;
            float f = 0.5f * qvv * qvv;
            y  = y + qvv * DTC + SIG0 * (dw0 + dw1 + dw2);
            Yv = Yv - f * DTC + zdw;
            float r = zdw - zdz;
            loss = fmaf(r, r, loss);
        }
        t += DTC;
    }
    if (owner) {
        float term = Yv - y * y;
        loss = fmaf(term, term, loss);
    } else {
        loss = 0.f;
    }

    // ---------------- reduction ----------------
    red[tx] = loss;
    __syncthreads();
    #pragma unroll
    for (int s = 128; s > 0; s >>= 1) {
        if (tx < s) red[tx] += red[tx + s];
        __syncthreads();
    }
    if (tx == 0) {
        g_partials[blockIdx.x] = red[0];
        __threadfence();
        unsigned int prev = atomicAdd(&g_count, 1u);
        is_last = (prev == gridDim.x - 1) ? 1 : 0;
    }
    __syncthreads();
    if (is_last) {
        __threadfence();
        red[tx] = (tx < 128) ? g_partials[tx] : 0.f;
        __syncthreads();
        #pragma unroll
        for (int s = 128; s > 0; s >>= 1) {
            if (tx < s) red[tx] += red[tx + s];
            __syncthreads();
        }
        if (tx == 0) {
            out[0] = red[0] * (1.0f / (float)NB);
            g_count = 0;               // reset for graph replay
        }
    }
}

extern "C" void kernel_launch(void* const* d_in, const int* in_sizes, int n_in,
                              void* d_out, int out_size)
{
    const float* y0  = (const float*)d_in[0];
    const float* Y0  = (const float*)d_in[1];
    const float* zW1 = (const float*)d_in[2];
    const float* zb1 = (const float*)d_in[3];
    const float* zW2 = (const float*)d_in[4];
    const float* zb2 = (const float*)d_in[5];
    const float* zW3 = (const float*)d_in[6];
    const float* zb3 = (const float*)d_in[7];
    const float* qW1 = (const float*)d_in[8];
    const float* qb1 = (const float*)d_in[9];
    const float* qW2 = (const float*)d_in[10];
    const float* qb2 = (const float*)d_in[11];
    const float* qW3 = (const float*)d_in[12];
    const float* qb3 = (const float*)d_in[13];
    const float* dW  = (const float*)d_in[14];
    const float* dZ  = (const float*)d_in[15];

    bsde_mma<<<128, 256>>>(y0, Y0, zW1, zb1, zW2, zb2, zW3, zb3,
                           qW1, qb1, qW2, qb2, qW3, qb3, dW, dZ,
                           (float*)d_out);
}

// round 15
// speedup vs baseline: 1.4565x; 1.4565x over previous
#include <cuda_runtime.h>
#include <cuda_fp16.h>

#define NB 16384
#define NSTEPS 100
#define DTC 0.01f
#define SQDT 0.1f
#define SIG0 0.5f

typedef unsigned int u32;
typedef unsigned long long u64;

__device__ __forceinline__ u32 h2u(__half2 h) {
    u32 r; *(__half2*)&r = h; return r;
}
__device__ __forceinline__ __half2 u2h(u32 u) {
    __half2 h; *(u32*)&h = u; return h;
}

__device__ __forceinline__ void mma16816(float* d, const u32 a0, const u32 a1,
                                         const u32 a2, const u32 a3,
                                         const u32 b0, const u32 b1) {
    asm volatile(
        "mma.sync.aligned.m16n8k16.row.col.f32.f16.f16.f32 "
        "{%0,%1,%2,%3}, {%4,%5,%6,%7}, {%8,%9}, {%0,%1,%2,%3};"
        : "+f"(d[0]), "+f"(d[1]), "+f"(d[2]), "+f"(d[3])
        : "r"(a0), "r"(a1), "r"(a2), "r"(a3), "r"(b0), "r"(b1));
}
// fp16-accumulator layer-1 MMA: D (2x half2) = A(16x8) * B(8x8) + D
__device__ __forceinline__ void mma16808h(u32* d, const u32 a0, const u32 a1,
                                          const u32 b0) {
    asm volatile(
        "mma.sync.aligned.m16n8k8.row.col.f16.f16.f16.f16 "
        "{%0,%1}, {%2,%3}, {%4}, {%0,%1};"
        : "+r"(d[0]), "+r"(d[1])
        : "r"(a0), "r"(a1), "r"(b0));
}

__device__ float g_partials[128];
__device__ unsigned int g_count = 0;

__global__ __launch_bounds__(256) void bsde_mma(
    const float* __restrict__ y0, const float* __restrict__ Y0,
    const float* __restrict__ zW1, const float* __restrict__ zb1,
    const float* __restrict__ zW2, const float* __restrict__ zb2,
    const float* __restrict__ zW3, const float* __restrict__ zb3,
    const float* __restrict__ qW1, const float* __restrict__ qb1,
    const float* __restrict__ qW2, const float* __restrict__ qb2,
    const float* __restrict__ qW3, const float* __restrict__ qb3,
    const float* __restrict__ dW, const float* __restrict__ dZ,
    float* __restrict__ out)
{
    // W2 staging (read once into regs): pos = n*16 + kt*4 + tq
    __shared__ u64 W2S[2][1024];
    // layer-3 B-fragments: [m][kt3][tq][g], u64 = (b0, b1)
    __shared__ u64 W3BS[2][4][4][8];
    // b2 as half2: [m][nt][tq] = (b2[8nt+2tq], b2[8nt+2tq+1])
    __shared__ u32 B2H[2][8][4];
    __shared__ float B3S[2][4];
    __shared__ float red[256];
    __shared__ int   is_last;

    const int tx = threadIdx.x;
    const int l  = tx & 31;
    const int w  = tx >> 5;          // 8 warps, each owns 16 paths
    const int g  = l >> 2;
    const int tq = l & 3;

    // ---------------- stage W2 ----------------
    for (int idx = tx; idx < 4096; idx += 256) {
        int k = idx >> 6, n = idx & 63;
        int kt = k >> 4, r = k & 15;
        int tt, slot;
        if (r < 8) { tt = r >> 1; slot = r & 1; }
        else       { tt = (r - 8) >> 1; slot = 2 + (r & 1); }
        int pos = n * 16 + kt * 4 + tt;
        ((__half*)&W2S[0][pos])[slot] = __float2half_rn(zW2[idx]);
        ((__half*)&W2S[1][pos])[slot] = __float2half_rn(qW2[idx]);
    }
    // ---------------- stage W3 B-fragments (zero-padded to 8 cols) ----------------
    if (tx < 256) {
        int idx = tx;
        int g5 = idx & 7, tq5 = (idx >> 3) & 3, kt5 = (idx >> 5) & 3, m5 = idx >> 7;
        int k0 = 16 * kt5 + 2 * tq5;
        float w00, w01, w10, w11;
        if (m5 == 0) {
            w00 = (g5 < 3) ? zW3[k0 * 3 + g5] : 0.f;
            w01 = (g5 < 3) ? zW3[(k0 + 1) * 3 + g5] : 0.f;
            w10 = (g5 < 3) ? zW3[(k0 + 8) * 3 + g5] : 0.f;
            w11 = (g5 < 3) ? zW3[(k0 + 9) * 3 + g5] : 0.f;
        } else {
            w00 = (g5 == 0) ? qW3[k0] : 0.f;
            w01 = (g5 == 0) ? qW3[k0 + 1] : 0.f;
            w10 = (g5 == 0) ? qW3[k0 + 8] : 0.f;
            w11 = (g5 == 0) ? qW3[k0 + 9] : 0.f;
        }
        u64 v = (u64)h2u(__floats2half2_rn(w00, w01))
              | ((u64)h2u(__floats2half2_rn(w10, w11)) << 32);
        W3BS[m5][kt5][tq5][g5] = v;
    }
    if (tx < 64) {
        int idx = tx;
        int tq6 = idx & 3, nt6 = (idx >> 2) & 7, m6 = idx >> 5;
        const float* b2 = m6 ? qb2 : zb2;
        int n = 8 * nt6 + 2 * tq6;
        B2H[m6][nt6][tq6] = h2u(__floats2half2_rn(b2[n], b2[n + 1]));
    }
    if (tx < 4) {
        B3S[0][tx] = (tx < 3) ? zb3[tx] : 0.f;
        B3S[1][tx] = (tx == 0) ? qb3[0] : 0.f;
    }
    __syncthreads();

    // ---------------- hoist BOTH MLPs' layer-2 B fragments to regs ----------------
    u32 Bzl[4][8], Bzh[4][8], Bql[4][8], Bqh[4][8];
    #pragma unroll
    for (int kt = 0; kt < 4; ++kt)
        #pragma unroll
        for (int nt = 0; nt < 8; ++nt) {
            u64 b = W2S[0][(8 * nt + g) * 16 + kt * 4 + tq];
            Bzl[kt][nt] = (u32)b;
            Bzh[kt][nt] = (u32)(b >> 32);
            u64 c = W2S[1][(8 * nt + g) * 16 + kt * 4 + tq];
            Bql[kt][nt] = (u32)c;
            Bqh[kt][nt] = (u32)(c >> 32);
        }

    // ---------------- layer-1 B fragments (K=8: rows t,y,1,0..) ----------------
    u32 W1Bf[2][8];
    #pragma unroll
    for (int m = 0; m < 2; ++m) {
        const float* W1 = m ? qW1 : zW1;
        const float* b1 = m ? qb1 : zb1;
        #pragma unroll
        for (int nt1 = 0; nt1 < 8; ++nt1) {
            int n = 8 * nt1 + g;
            u32 v = 0;
            if (tq == 0)      v = h2u(__floats2half2_rn(W1[n], W1[64 + n]));
            else if (tq == 1) v = h2u(__floats2half2_rn(b1[n], 0.f));
            W1Bf[m][nt1] = v;
        }
    }

    // ---------------- per-path state: lane l < 16 owns path base + l ----------------
    const int path = blockIdx.x * 128 + w * 16 + (l & 15);
    const bool owner = (l < 16);
    float y = y0[0], Yv = Y0[0], t = 0.f, loss = 0.f;
    const float* dWp = dW + path * 3;
    const float* dZp = dZ + path * 3;

    #pragma unroll 1
    for (int i = 0; i < NSTEPS; ++i) {
        float dw0 = 0.f, dw1 = 0.f, dw2 = 0.f, dz0 = 0.f, dz1 = 0.f, dz2 = 0.f;
        if (owner) {
            dw0 = dWp[0] * SQDT; dw1 = dWp[1] * SQDT; dw2 = dWp[2] * SQDT;
            dz0 = dZp[0] * SQDT; dz1 = dZp[1] * SQDT; dz2 = dZp[2] * SQDT;
        }
        dWp += NB * 3; dZp += NB * 3;

        // y for rows g, g+8 of this warp's 16-path tile
        float yg  = __shfl_sync(0xffffffffu, y, g, 32);
        float yg8 = __shfl_sync(0xffffffffu, y, g + 8, 32);

        // layer-1 A fragment: A[p][k] = (t, y_p, 1, 0...) -- shared by z and q
        u32 a1_0, a1_1;
        if (tq == 0) {
            a1_0 = h2u(__floats2half2_rn(t, yg));
            a1_1 = h2u(__floats2half2_rn(t, yg8));
        } else if (tq == 1) {
            a1_0 = 0x00003C00u;   // half2(1.0, 0.0)
            a1_1 = 0x00003C00u;
        } else {
            a1_0 = 0u;
            a1_1 = 0u;
        }

        // ---- layer 1: fp16-accum MMAs, both MLPs (16 independent) ----
        u32 A2[2][4][4];
        const __half2 zh2 = __floats2half2_rn(0.f, 0.f);
        #pragma unroll
        for (int m = 0; m < 2; ++m) {
            #pragma unroll
            for (int kt = 0; kt < 4; ++kt) {
                u32 Da[2] = {0u, 0u}, Db[2] = {0u, 0u};
                mma16808h(Da, a1_0, a1_1, W1Bf[m][2 * kt]);
                mma16808h(Db, a1_0, a1_1, W1Bf[m][2 * kt + 1]);
                A2[m][kt][0] = h2u(__hmax2(u2h(Da[0]), zh2));
                A2[m][kt][1] = h2u(__hmax2(u2h(Da[1]), zh2));
                A2[m][kt][2] = h2u(__hmax2(u2h(Db[0]), zh2));
                A2[m][kt][3] = h2u(__hmax2(u2h(Db[1]), zh2));
            }
        }

        // ---- layers 2+3 in kt3 groups: 4 indep L2 chains/group; L3 MMA per
        //      group whose latency hides under the NEXT group's L2 MMAs ----
        float D3z[4] = {0.f, 0.f, 0.f, 0.f};
        float D3q[4] = {0.f, 0.f, 0.f, 0.f};
        #pragma unroll
        for (int g3 = 0; g3 < 4; ++g3) {
            const int ntA = 2 * g3, ntB = 2 * g3 + 1;
            float dza[4] = {0.f, 0.f, 0.f, 0.f}, dzb[4] = {0.f, 0.f, 0.f, 0.f};
            float dqa[4] = {0.f, 0.f, 0.f, 0.f}, dqb[4] = {0.f, 0.f, 0.f, 0.f};
            #pragma unroll
            for (int kt = 0; kt < 4; ++kt) {
                mma16816(dza, A2[0][kt][0], A2[0][kt][1], A2[0][kt][2], A2[0][kt][3],
                         Bzl[kt][ntA], Bzh[kt][ntA]);
                mma16816(dqa, A2[1][kt][0], A2[1][kt][1], A2[1][kt][2], A2[1][kt][3],
                         Bql[kt][ntA], Bqh[kt][ntA]);
                mma16816(dzb, A2[0][kt][0], A2[0][kt][1], A2[0][kt][2], A2[0][kt][3],
                         Bzl[kt][ntB], Bzh[kt][ntB]);
                mma16816(dqb, A2[1][kt][0], A2[1][kt][1], A2[1][kt][2], A2[1][kt][3],
                         Bql[kt][ntB], Bqh[kt][ntB]);
            }
            // +b2, relu, pack -> layer-3 A fragment for kt3 = g3
            u32 A3z[4], A3q[4];
            {
                __half2 b2a = u2h(B2H[0][ntA][tq]);
                __half2 b2b = u2h(B2H[0][ntB][tq]);
                A3z[0] = h2u(__hmax2(__hadd2(__floats2half2_rn(dza[0], dza[1]), b2a), zh2));
                A3z[1] = h2u(__hmax2(__hadd2(__floats2half2_rn(dza[2], dza[3]), b2a), zh2));
                A3z[2] = h2u(__hmax2(__hadd2(__floats2half2_rn(dzb[0], dzb[1]), b2b), zh2));
                A3z[3] = h2u(__hmax2(__hadd2(__floats2half2_rn(dzb[2], dzb[3]), b2b), zh2));
                b2a = u2h(B2H[1][ntA][tq]);
                b2b = u2h(B2H[1][ntB][tq]);
                A3q[0] = h2u(__hmax2(__hadd2(__floats2half2_rn(dqa[0], dqa[1]), b2a), zh2));
                A3q[1] = h2u(__hmax2(__hadd2(__floats2half2_rn(dqa[2], dqa[3]), b2a), zh2));
                A3q[2] = h2u(__hmax2(__hadd2(__floats2half2_rn(dqb[0], dqb[1]), b2b), zh2));
                A3q[3] = h2u(__hmax2(__hadd2(__floats2half2_rn(dqb[2], dqb[3]), b2b), zh2));
            }
            // layer-3 MMAs for this group (accumulate into D3 chains)
            u64 w3z = W3BS[0][g3][tq][g];
            mma16816(D3z, A3z[0], A3z[1], A3z[2], A3z[3], (u32)w3z, (u32)(w3z >> 32));
            u64 w3q = W3BS[1][g3][tq][g];
            mma16816(D3q, A3q[0], A3q[1], A3q[2], A3q[3], (u32)w3q, (u32)(w3q >> 32));
        }

        // ---- redistribute: path p reads D3[p][col] ----
        // D3 frag: d0=(g,2tq) d1=(g,2tq+1) d2=(g+8,2tq) d3=(g+8,2tq+1)
        const int srcA = 4 * (l & 7);
        const bool hi8 = (l & 8) != 0;
        float va, vb;
        va = __shfl_sync(0xffffffffu, D3z[0], srcA, 32);
        vb = __shfl_sync(0xffffffffu, D3z[2], srcA, 32);
        float zo0 = (hi8 ? vb : va) + B3S[0][0];
        va = __shfl_sync(0xffffffffu, D3z[1], srcA, 32);
        vb = __shfl_sync(0xffffffffu, D3z[3], srcA, 32);
        float zo1 = (hi8 ? vb : va) + B3S[0][1];
        va = __shfl_sync(0xffffffffu, D3z[0], srcA + 1, 32);
        vb = __shfl_sync(0xffffffffu, D3z[2], srcA + 1, 32);
        float zo2 = (hi8 ? vb : va) + B3S[0][2];
        va = __shfl_sync(0xffffffffu, D3q[0], srcA, 32);
        vb = __shfl_sync(0xffffffffu, D3q[2], srcA, 32);
        float qvv = (hi8 ? vb : va) + B3S[1][0];

        // ---- SDE / BSDE update (residual = z.dw - z.dz; Y cancels) ----
        if (owner) {
            float zdw = zo0 * dw0 + zo1 * dw1 + zo2 * dw2;
            float zdz = zo0 * dz0 + zo1 * dz1 + zo2 * dz2;
            float f = 0.5f * qvv * qvv;
            y  = y + qvv * DTC + SIG0 * (dw0 + dw1 + dw2);
            Yv = Yv - f * DTC + zdw;
            float r = zdw - zdz;
            loss = fmaf(r, r, loss);
        }
        t += DTC;
    }
    if (owner) {
        float term = Yv - y * y;
        loss = fmaf(term, term, loss);
    } else {
        loss = 0.f;
    }

    // ---------------- reduction ----------------
    red[tx] = loss;
    __syncthreads();
    #pragma unroll
    for (int s = 128; s > 0; s >>= 1) {
        if (tx < s) red[tx] += red[tx + s];
        __syncthreads();
    }
    if (tx == 0) {
        g_partials[blockIdx.x] = red[0];
        __threadfence();
        unsigned int prev = atomicAdd(&g_count, 1u);
        is_last = (prev == gridDim.x - 1) ? 1 : 0;
    }
    __syncthreads();
    if (is_last) {
        __threadfence();
        red[tx] = (tx < 128) ? g_partials[tx] : 0.f;
        __syncthreads();
        #pragma unroll
        for (int s = 128; s > 0; s >>= 1) {
            if (tx < s) red[tx] += red[tx + s];
            __syncthreads();
        }
        if (tx == 0) {
            out[0] = red[0] * (1.0f / (float)NB);
            g_count = 0;               // reset for graph replay
        }
    }
}

extern "C" void kernel_launch(void* const* d_in, const int* in_sizes, int n_in,
                              void* d_out, int out_size)
{
    const float* y0  = (const float*)d_in[0];
    const float* Y0  = (const float*)d_in[1];
    const float* zW1 = (const float*)d_in[2];
    const float* zb1 = (const float*)d_in[3];
    const float* zW2 = (const float*)d_in[4];
    const float* zb2 = (const float*)d_in[5];
    const float* zW3 = (const float*)d_in[6];
    const float* zb3 = (const float*)d_in[7];
    const float* qW1 = (const float*)d_in[8];
    const float* qb1 = (const float*)d_in[9];
    const float* qW2 = (const float*)d_in[10];
    const float* qb2 = (const float*)d_in[11];
    const float* qW3 = (const float*)d_in[12];
    const float* qb3 = (const float*)d_in[13];
    const float* dW  = (const float*)d_in[14];
    const float* dZ  = (const float*)d_in[15];

    bsde_mma<<<128, 256>>>(y0, Y0, zW1, zb1, zW2, zb2, zW3, zb3,
                           qW1, qb1, qW2, qb2, qW3, qb3, dW, dZ,
                           (float*)d_out);
}